// round 1
// baseline (speedup 1.0000x reference)
#include <cuda_runtime.h>
#include <cuda_bf16.h>

// GraphAddPooling: out[g] = sum_{i: batch[i]==g} x[i]
// x: [200000, 256] fp32, batch: sorted segment ids (int32 or int64 — detected),
// out: [512, 256] fp32.
//
// Strategy: batch is sorted -> segments are contiguous row ranges. Each
// 64-lane group (one float4 per lane = one full 1024B row, perfectly
// coalesced) walks a strided stream of rows, accumulating the running
// segment sum in registers and flushing with atomicAdd only at segment
// boundaries and stream end. ~1.7M total atomics vs 51M for the naive
// approach. HBM-read-bound: ~205 MB -> ~30 us floor.

#define NCOLS 256
#define VCOLS (NCOLS / 4)   // 64 float4 per row
#define NSEG 512
#define RPB 169             // rows per block
#define GRID_MAIN 1184      // ceil(200000 / 169); 8 CTAs/SM on 148 SMs

__global__ void gap_zero_kernel(float4* __restrict__ out, int n4) {
    int i = blockIdx.x * blockDim.x + threadIdx.x;
    if (i < n4) out[i] = make_float4(0.f, 0.f, 0.f, 0.f);
}

__global__ __launch_bounds__(256, 8) void gap_segsum_kernel(
    const float4* __restrict__ x,
    const int* __restrict__ b32,   // batch viewed as int32 words
    float* __restrict__ out,
    int nrows)
{
    const int lane = threadIdx.x;   // 0..63 : column group (float4)
    const int ys   = threadIdx.y;   // 0..3  : row stream within block

    // Detect int64 vs int32 batch. Values are sorted, < 512. If stored as
    // int64 (little-endian), the int32 word at index nrows-1 is a high word
    // (== 0); if int32, it's the last (largest) segment id (> 0 w.h.p.).
    // For int64 we read the low word at index 2*r (ids < 2^31 so low word
    // equals the value).
    const int shift = (b32[nrows - 1] == 0) ? 1 : 0;

    int start = blockIdx.x * RPB;
    int end   = start + RPB;
    if (end > nrows) end = nrows;

    float4 acc = make_float4(0.f, 0.f, 0.f, 0.f);
    int cur = -1;

    int r = start + ys;
    int g = 0;
    float4 v = make_float4(0.f, 0.f, 0.f, 0.f);
    if (r < end) {
        g = b32[r << shift];
        v = x[(size_t)r * VCOLS + lane];
    }

    while (r < end) {
        // Prefetch next iteration (MLP=2: hide DRAM latency).
        int rn = r + 4;
        int gn = 0;
        float4 vn = make_float4(0.f, 0.f, 0.f, 0.f);
        if (rn < end) {
            gn = b32[rn << shift];
            vn = x[(size_t)rn * VCOLS + lane];
        }

        if (g != cur) {
            if (cur >= 0) {
                float* o = out + (size_t)cur * NCOLS + lane * 4;
                atomicAdd(o + 0, acc.x);
                atomicAdd(o + 1, acc.y);
                atomicAdd(o + 2, acc.z);
                atomicAdd(o + 3, acc.w);
            }
            cur = g;
            acc = v;
        } else {
            acc.x += v.x; acc.y += v.y; acc.z += v.z; acc.w += v.w;
        }

        r = rn; g = gn; v = vn;
    }

    if (cur >= 0) {
        float* o = out + (size_t)cur * NCOLS + lane * 4;
        atomicAdd(o + 0, acc.x);
        atomicAdd(o + 1, acc.y);
        atomicAdd(o + 2, acc.z);
        atomicAdd(o + 3, acc.w);
    }
}

extern "C" void kernel_launch(void* const* d_in, const int* in_sizes, int n_in,
                              void* d_out, int out_size) {
    const float4* x  = (const float4*)d_in[0];
    const int* batch = (const int*)d_in[1];   // int32 view; width detected on device
    float* out = (float*)d_out;

    const int nrows = in_sizes[1];            // 200000 (element count of batch)
    const int n4 = out_size / 4;              // 512*256/4 = 32768 float4

    // Zero the (poisoned) output, then accumulate. Stream-ordered, capturable.
    gap_zero_kernel<<<(n4 + 255) / 256, 256>>>((float4*)out, n4);

    dim3 block(64, 4);
    gap_segsum_kernel<<<GRID_MAIN, block>>>(x, batch, out, nrows);
}

// round 2
// speedup vs baseline: 1.0548x; 1.0548x over previous
#include <cuda_runtime.h>
#include <cuda_bf16.h>

// GraphAddPooling: out[g] = sum_{i: batch[i]==g} x[i]
// x: [200000, 256] fp32, batch: sorted (int32 or int64, detected on device),
// out: [512, 256] fp32.
//
// One block per segment. batch sorted => segment g = rows
// [lower_bound(g), lower_bound(g+1)). Each block:
//   1. two warps do a 32-ary cooperative lower_bound (5 chained probes)
//   2. 8 row-streams x 64 lanes (one float4/lane = full 1024B row,
//      perfectly coalesced) stream-sum the rows with depth-2 prefetch
//   3. smem tree-combine, plain STG to out[g]  (no atomics, no zero pass)

#define NCOLS   256
#define VCOLS   64      // float4 per row
#define STREAMS 8
#define TPB     512     // 64 lanes x 8 streams

// Warp-cooperative lower_bound over sorted int segment ids.
// 'shift' = 1 when batch is int64 (probe low words), 0 when int32.
__device__ __forceinline__ int warp_lower_bound(const int* __restrict__ b,
                                                int shift, int n,
                                                int target, int lane) {
    int lo = 0, rem = n;
    while (rem > 0) {
        int chunk = (rem + 32) / 33;                 // 33-way partition
        long p = (long)lo + (long)chunk * (lane + 1) - 1;  // end of lane's chunk
        bool lt = false;
        if (p < (long)lo + rem) lt = (b[p << shift] < target);
        unsigned m = __ballot_sync(0xffffffffu, lt);
        int k = __popc(m);                           // k full chunks < target
        lo += k * chunk;
        int r2 = rem - k * chunk;
        rem = (r2 <= 0) ? 0 : ((r2 >= chunk) ? (chunk - 1) : r2);
    }
    return lo;   // first index with b[i] >= target (== n if none)
}

__global__ __launch_bounds__(TPB, 4) void gap_seg_kernel(
    const float4* __restrict__ x,
    const int* __restrict__ b32,     // batch viewed as int32 words
    float4* __restrict__ out,
    int nrows)
{
    __shared__ int    s_bounds[2];
    __shared__ float4 s_part[STREAMS][VCOLS];

    const int g     = blockIdx.x;
    const int tid   = threadIdx.x;
    const int lane  = tid & 63;      // float4 column group
    const int ys    = tid >> 6;      // row stream 0..7
    const int wlane = tid & 31;
    const int wid   = tid >> 5;

    // int64 vs int32 batch: sorted ids < 512, so if stored as int64 the
    // int32 word at index nrows-1 is a high word (== 0).
    const int shift = (b32[nrows - 1] == 0) ? 1 : 0;

    if (wid < 2) {
        int r = warp_lower_bound(b32, shift, nrows, g + wid, wlane);
        if (wlane == 0) s_bounds[wid] = r;
    }
    __syncthreads();
    const int lo = s_bounds[0];
    const int hi = s_bounds[1];

    // Stream rows lo+ys, lo+ys+8, ... with depth-2 prefetch.
    float4 acc = make_float4(0.f, 0.f, 0.f, 0.f);
    int r = lo + ys;
    float4 v = make_float4(0.f, 0.f, 0.f, 0.f);
    if (r < hi) v = __ldcs(x + (size_t)r * VCOLS + lane);

    while (r < hi) {
        int rn = r + STREAMS;
        float4 vn = make_float4(0.f, 0.f, 0.f, 0.f);
        if (rn < hi) vn = __ldcs(x + (size_t)rn * VCOLS + lane);
        acc.x += v.x; acc.y += v.y; acc.z += v.z; acc.w += v.w;
        r = rn; v = vn;
    }

    s_part[ys][lane] = acc;
    __syncthreads();

    if (ys == 0) {
        float4 a = s_part[0][lane];
        #pragma unroll
        for (int s = 1; s < STREAMS; s++) {
            float4 b = s_part[s][lane];
            a.x += b.x; a.y += b.y; a.z += b.z; a.w += b.w;
        }
        out[(size_t)g * VCOLS + lane] = a;   // unconditional: empty segs get 0
    }
}

extern "C" void kernel_launch(void* const* d_in, const int* in_sizes, int n_in,
                              void* d_out, int out_size) {
    const float4* x  = (const float4*)d_in[0];
    const int* batch = (const int*)d_in[1];
    float4* out      = (float4*)d_out;

    const int nrows = in_sizes[1];        // 200000
    const int nseg  = out_size / NCOLS;   // 512

    gap_seg_kernel<<<nseg, TPB>>>(x, batch, out, nrows);
}